// round 14
// baseline (speedup 1.0000x reference)
#include <cuda_runtime.h>
#include <cstdint>

// Problem dims (fixed by the reference)
static constexpr int M = 8192;
static constexpr int N = 4096;
static constexpr int K = 4096;

// Tiling: 128x128 CTA tile, 512 threads (16 warps, 4x4 of 32x32 warp tiles),
// BK=64, 3-stage ring -> 2 CTAs/SM = 32 warps/SM.
static constexpr int BM = 128;
static constexpr int BN = 128;
static constexpr int BK = 64;            // k-chunk bytes
static constexpr int LDSS = 80;          // smem row stride (64 data + 16 pad)
static constexpr int KT = K / BK;        // 64 k-chunks
static constexpr int STAGES = 3;
static constexpr int A_ST = BM * LDSS;   // 10240 B
static constexpr int B_ST = BN * LDSS;   // 10240 B
static constexpr int STAGE_BYTES = A_ST + B_ST;         // 20480 B
static constexpr int SMEM_DYN = STAGES * STAGE_BYTES;   // 61440 B (x2 = 123 KB/SM)

// int8 scratch (pre-quantized inputs). __device__ globals = allowed scratch.
__device__ int8_t g_xq[(size_t)M * K];   // 32 MB
__device__ int8_t g_wq[(size_t)N * K];   // 16 MB

__device__ __forceinline__ void cp_async16(void* smem_dst, const void* gmem_src) {
    uint32_t s = (uint32_t)__cvta_generic_to_shared(smem_dst);
    asm volatile("cp.async.cg.shared.global [%0], [%1], 16;\n" :: "r"(s), "l"(gmem_src));
}
__device__ __forceinline__ void cp_async_commit() {
    asm volatile("cp.async.commit_group;\n");
}
template <int NN>
__device__ __forceinline__ void cp_async_wait() {
    asm volatile("cp.async.wait_group %0;\n" :: "n"(NN));
}

__device__ __forceinline__ void mma_s8(int32_t* c, const uint32_t* a, const uint32_t* b) {
    asm volatile(
        "mma.sync.aligned.m16n8k32.row.col.s32.s8.s8.s32 "
        "{%0,%1,%2,%3}, {%4,%5,%6,%7}, {%8,%9}, {%0,%1,%2,%3};\n"
        : "+r"(c[0]), "+r"(c[1]), "+r"(c[2]), "+r"(c[3])
        : "r"(a[0]), "r"(a[1]), "r"(a[2]), "r"(a[3]),
          "r"(b[0]), "r"(b[1]));
}

// ---------------------------------------------------------------------------
// Pre-pass: dtype-agnostic word decode -> packed int8 (proven math).
// 16 elements per thread; streaming loads. At its bandwidth floor (~40 us).
// ---------------------------------------------------------------------------
__device__ __forceinline__ int8_t decode_q(uint32_t bits) {
    int iv = (int)bits;
    if ((unsigned)(iv + 128) <= 255u) return (int8_t)iv;
    float f = __int_as_float((int)bits);
    int v = __float2int_rn(f);
    v = min(127, max(-128, v));
    return (int8_t)v;
}

__device__ __forceinline__ uint32_t decode4(uint4 v) {
    uint32_t b0 = (uint8_t)decode_q(v.x);
    uint32_t b1 = (uint8_t)decode_q(v.y);
    uint32_t b2 = (uint8_t)decode_q(v.z);
    uint32_t b3 = (uint8_t)decode_q(v.w);
    return b0 | (b1 << 8) | (b2 << 16) | (b3 << 24);
}

__global__ void quantize_all_kernel(const uint4* __restrict__ x_in,
                                    const uint4* __restrict__ w_in,
                                    float* __restrict__ out,
                                    const float* __restrict__ o_scale,
                                    int body, int out_total)
{
    const int n16x = (M * K) / 16;
    const int n16w = (N * K) / 16;
    int i = blockIdx.x * blockDim.x + threadIdx.x;
    if (i < n16x) {
        uint4 o;
        o.x = decode4(__ldcs(&x_in[i * 4 + 0]));
        o.y = decode4(__ldcs(&x_in[i * 4 + 1]));
        o.z = decode4(__ldcs(&x_in[i * 4 + 2]));
        o.w = decode4(__ldcs(&x_in[i * 4 + 3]));
        ((uint4*)g_xq)[i] = o;
    } else if (i < n16x + n16w) {
        int j = i - n16x;
        uint4 o;
        o.x = decode4(__ldcs(&w_in[j * 4 + 0]));
        o.y = decode4(__ldcs(&w_in[j * 4 + 1]));
        o.z = decode4(__ldcs(&w_in[j * 4 + 2]));
        o.w = decode4(__ldcs(&w_in[j * 4 + 3]));
        ((uint4*)g_wq)[j] = o;
    }
    if (blockIdx.x == 0) {
        for (int idx = body + threadIdx.x; idx < out_total; idx += blockDim.x)
            out[idx] = o_scale[0];
    }
}

// ---------------------------------------------------------------------------
// int8 GEMM: C[m,n] = sum_k A[m,k]*B[n,k]. 128x128 CTA tile, 512 threads,
// BK=64, 3-stage ring, one __syncthreads per k-tile, loads after the barrier.
// 16 warps: 4 M-slabs x 4 N-slabs of 32x32 each. acc = 32 regs/thread.
// ---------------------------------------------------------------------------
__global__ __launch_bounds__(512, 2)
void int8_gemm_kernel(const float* __restrict__ scale_x,
                      const float* __restrict__ w_scale,
                      const float* __restrict__ o_scale,
                      float* __restrict__ C)             // [M, N] f32 output
{
    extern __shared__ int8_t smem[];
    const int8_t* __restrict__ A = g_xq;
    const int8_t* __restrict__ B = g_wq;

    const int tid  = threadIdx.x;
    const int warp = tid >> 5;
    const int lane = tid & 31;
    const int warpM = warp >> 2;      // 0..3 -> 32-row slab
    const int warpN = warp & 3;       // 0..3 -> 32-col slab
    const int g = lane >> 2;          // group id 0..7
    const int q = lane & 3;           // thread-in-group 0..3

    const int bm = blockIdx.y * BM;
    const int bn = blockIdx.x * BN;

    // cp.async mapping: A = 128x64B = 512 x16B chunks (1/thread);
    //                   B = 128x64B = 512 x16B chunks (1/thread).
    auto load_tile = [&](int stage, int kt) {
        int8_t* smA = smem + stage * STAGE_BYTES;
        int8_t* smB = smA + A_ST;
        const int k0 = kt * BK;
        const int row = tid >> 2, col = (tid & 3) * 16;
        cp_async16(&smA[row * LDSS + col], A + (size_t)(bm + row) * K + k0 + col);
        cp_async16(&smB[row * LDSS + col], B + (size_t)(bn + row) * K + k0 + col);
        cp_async_commit();
    };

    int32_t acc[2][4][4];
    #pragma unroll
    for (int mt = 0; mt < 2; mt++)
        #pragma unroll
        for (int nt = 0; nt < 4; nt++)
            #pragma unroll
            for (int i = 0; i < 4; i++)
                acc[mt][nt][i] = 0;

    // Prologue: stages 0,1
    load_tile(0, 0);
    load_tile(1, 1);

    for (int kt = 0; kt < KT; kt++) {
        if (kt + 2 < KT) cp_async_wait<1>();
        else             cp_async_wait<0>();
        __syncthreads();
        if (kt + 2 < KT) load_tile((kt + 2) % STAGES, kt + 2);

        const int st = kt % STAGES;
        const int8_t* smA = smem + st * STAGE_BYTES;
        const int8_t* smB = smA + A_ST;

        #pragma unroll
        for (int ki = 0; ki < 2; ki++) {        // two k32 steps inside BK=64
            const int kc = ki * 32 + q * 4;

            uint32_t af[2][4];
            #pragma unroll
            for (int mt = 0; mt < 2; mt++) {
                const int row = warpM * 32 + mt * 16 + g;
                const int8_t* base = &smA[row * LDSS + kc];
                af[mt][0] = *(const uint32_t*)(base);
                af[mt][1] = *(const uint32_t*)(base + 8 * LDSS);
                af[mt][2] = *(const uint32_t*)(base + 16);
                af[mt][3] = *(const uint32_t*)(base + 8 * LDSS + 16);
            }
            uint32_t bf[4][2];
            #pragma unroll
            for (int nt = 0; nt < 4; nt++) {
                const int nrow = warpN * 32 + nt * 8 + g;
                const int8_t* base = &smB[nrow * LDSS + kc];
                bf[nt][0] = *(const uint32_t*)(base);
                bf[nt][1] = *(const uint32_t*)(base + 16);
            }
            #pragma unroll
            for (int mt = 0; mt < 2; mt++)
                #pragma unroll
                for (int nt = 0; nt < 4; nt++)
                    mma_s8(acc[mt][nt], af[mt], bf[nt]);
        }
    }

    // Epilogue: dequant -> RNE -> clamp -> streaming store as FLOAT.
    const float scale = scale_x[0] * w_scale[0] / o_scale[0];

    #pragma unroll
    for (int mt = 0; mt < 2; mt++) {
        #pragma unroll
        for (int nt = 0; nt < 4; nt++) {
            const int row0 = bm + warpM * 32 + mt * 16 + g;
            const int col  = bn + warpN * 32 + nt * 8 + q * 2;
            #pragma unroll
            for (int half = 0; half < 2; half++) {
                const int row = row0 + half * 8;
                int v0 = __float2int_rn((float)acc[mt][nt][half * 2 + 0] * scale);
                int v1 = __float2int_rn((float)acc[mt][nt][half * 2 + 1] * scale);
                v0 = min(127, max(-128, v0));
                v1 = min(127, max(-128, v1));
                float2 o;
                o.x = (float)v0;
                o.y = (float)v1;
                __stcs((float2*)(C + (size_t)row * N + col), o);
            }
        }
    }
}

extern "C" void kernel_launch(void* const* d_in, const int* in_sizes, int n_in,
                              void* d_out, int out_size)
{
    // Identify inputs by element count (robust to metadata ordering).
    const void* x_ptr = nullptr;
    const void* w_ptr = nullptr;
    const float* scalars[3] = {nullptr, nullptr, nullptr};
    int ns = 0;
    for (int i = 0; i < n_in; i++) {
        long long sz = in_sizes[i];
        if (sz == (long long)M * K)      x_ptr = d_in[i];
        else if (sz == (long long)N * K) w_ptr = d_in[i];
        else if (ns < 3)                 scalars[ns++] = (const float*)d_in[i];
    }
    const float* scale_x = scalars[0];   // order: scale_x, weight_scale, out_scale
    const float* w_scale = scalars[1];
    const float* o_scale = scalars[2];
    float* out = (float*)d_out;

    static bool attr_done = false;
    if (!attr_done) {
        cudaFuncSetAttribute(int8_gemm_kernel,
                             cudaFuncAttributeMaxDynamicSharedMemorySize, SMEM_DYN);
        attr_done = true;
    }

    // Launch 1: decode inputs to int8 scratch + write output tail.
    {
        const int body = M * N;
        int n16 = (M * K + N * K) / 16;
        quantize_all_kernel<<<(n16 + 255) / 256, 256>>>(
            (const uint4*)x_ptr, (const uint4*)w_ptr,
            out, o_scale, body, out_size);
    }

    // Launch 2: the GEMM.
    dim3 grid(N / BN, M / BM);   // (32, 64) = 2048 CTAs
    int8_gemm_kernel<<<grid, 512, SMEM_DYN>>>(scale_x, w_scale, o_scale, out);
}

// round 15
// speedup vs baseline: 1.0577x; 1.0577x over previous
#include <cuda_runtime.h>
#include <cstdint>

// Problem dims (fixed by the reference)
static constexpr int M = 8192;
static constexpr int N = 4096;
static constexpr int K = 4096;

// Tiling: 128x64 CTA tile, BK=64, 3-stage ring, 3 CTAs/SM (24 warps in three
// independent 8-warp barrier domains) — best measured configuration (R10).
static constexpr int BM = 128;
static constexpr int BN = 64;
static constexpr int BK = 64;            // k-chunk bytes
static constexpr int LDSS = 80;          // smem row stride (64 data + 16 pad)
static constexpr int KT = K / BK;        // 64 k-chunks
static constexpr int STAGES = 3;
static constexpr int A_ST = BM * LDSS;   // 10240 B
static constexpr int B_ST = BN * LDSS;   // 5120 B
static constexpr int STAGE_BYTES = A_ST + B_ST;         // 15360 B
static constexpr int SMEM_DYN = STAGES * STAGE_BYTES;   // 46080 B

// int8 scratch (pre-quantized inputs). __device__ globals = allowed scratch.
__device__ int8_t g_xq[(size_t)M * K];   // 32 MB
__device__ int8_t g_wq[(size_t)N * K];   // 16 MB

__device__ __forceinline__ void cp_async16(void* smem_dst, const void* gmem_src) {
    uint32_t s = (uint32_t)__cvta_generic_to_shared(smem_dst);
    asm volatile("cp.async.cg.shared.global [%0], [%1], 16;\n" :: "r"(s), "l"(gmem_src));
}
__device__ __forceinline__ void cp_async_commit() {
    asm volatile("cp.async.commit_group;\n");
}
template <int NN>
__device__ __forceinline__ void cp_async_wait() {
    asm volatile("cp.async.wait_group %0;\n" :: "n"(NN));
}

__device__ __forceinline__ void mma_s8(int32_t* c, const uint32_t* a, const uint32_t* b) {
    asm volatile(
        "mma.sync.aligned.m16n8k32.row.col.s32.s8.s8.s32 "
        "{%0,%1,%2,%3}, {%4,%5,%6,%7}, {%8,%9}, {%0,%1,%2,%3};\n"
        : "+r"(c[0]), "+r"(c[1]), "+r"(c[2]), "+r"(c[3])
        : "r"(a[0]), "r"(a[1]), "r"(a[2]), "r"(a[3]),
          "r"(b[0]), "r"(b[1]));
}

// ---------------------------------------------------------------------------
// Pre-pass: dtype-agnostic word decode -> packed int8 (proven math).
// 16 elements per thread; streaming loads (inputs read exactly once).
// At its HBM floor (~40 us for 240 MB).
// ---------------------------------------------------------------------------
__device__ __forceinline__ int8_t decode_q(uint32_t bits) {
    int iv = (int)bits;
    if ((unsigned)(iv + 128) <= 255u) return (int8_t)iv;
    float f = __int_as_float((int)bits);
    int v = __float2int_rn(f);
    v = min(127, max(-128, v));
    return (int8_t)v;
}

__device__ __forceinline__ uint32_t decode4(uint4 v) {
    uint32_t b0 = (uint8_t)decode_q(v.x);
    uint32_t b1 = (uint8_t)decode_q(v.y);
    uint32_t b2 = (uint8_t)decode_q(v.z);
    uint32_t b3 = (uint8_t)decode_q(v.w);
    return b0 | (b1 << 8) | (b2 << 16) | (b3 << 24);
}

__global__ void quantize_all_kernel(const uint4* __restrict__ x_in,
                                    const uint4* __restrict__ w_in,
                                    float* __restrict__ out,
                                    const float* __restrict__ o_scale,
                                    int body, int out_total)
{
    const int n16x = (M * K) / 16;
    const int n16w = (N * K) / 16;
    int i = blockIdx.x * blockDim.x + threadIdx.x;
    if (i < n16x) {
        uint4 o;
        o.x = decode4(__ldcs(&x_in[i * 4 + 0]));
        o.y = decode4(__ldcs(&x_in[i * 4 + 1]));
        o.z = decode4(__ldcs(&x_in[i * 4 + 2]));
        o.w = decode4(__ldcs(&x_in[i * 4 + 3]));
        ((uint4*)g_xq)[i] = o;
    } else if (i < n16x + n16w) {
        int j = i - n16x;
        uint4 o;
        o.x = decode4(__ldcs(&w_in[j * 4 + 0]));
        o.y = decode4(__ldcs(&w_in[j * 4 + 1]));
        o.z = decode4(__ldcs(&w_in[j * 4 + 2]));
        o.w = decode4(__ldcs(&w_in[j * 4 + 3]));
        ((uint4*)g_wq)[j] = o;
    }
    if (blockIdx.x == 0) {
        for (int idx = body + threadIdx.x; idx < out_total; idx += blockDim.x)
            out[idx] = o_scale[0];
    }
}

// ---------------------------------------------------------------------------
// int8 GEMM: C[m,n] = sum_k A[m,k]*B[n,k]. 128x64 CTA tile, BK=64,
// 3-stage ring, one __syncthreads per k-tile, loads after the barrier.
// 8 warps: 4 M-slabs x 2 N-slabs of 32x32 each. acc = 32 regs/thread.
// (Bit-for-bit the R10 mainloop — best measured: GEMM 1778 us, tensor 97.5%.)
// ---------------------------------------------------------------------------
__global__ __launch_bounds__(256, 3)
void int8_gemm_kernel(const float* __restrict__ scale_x,
                      const float* __restrict__ w_scale,
                      const float* __restrict__ o_scale,
                      float* __restrict__ C)             // [M, N] f32 output
{
    extern __shared__ int8_t smem[];
    const int8_t* __restrict__ A = g_xq;
    const int8_t* __restrict__ B = g_wq;

    const int tid  = threadIdx.x;
    const int warp = tid >> 5;
    const int lane = tid & 31;
    const int warpM = warp >> 1;      // 0..3 -> 32-row slab
    const int warpN = warp & 1;       // 0..1 -> 32-col slab
    const int g = lane >> 2;          // group id 0..7
    const int q = lane & 3;           // thread-in-group 0..3

    const int bm = blockIdx.y * BM;
    const int bn = blockIdx.x * BN;

    // cp.async mapping: A = 128x64B = 512 x16B chunks (2/thread);
    //                   B =  64x64B = 256 x16B chunks (1/thread).
    auto load_tile = [&](int stage, int kt) {
        int8_t* smA = smem + stage * STAGE_BYTES;
        int8_t* smB = smA + A_ST;
        const int k0 = kt * BK;
        #pragma unroll
        for (int i = 0; i < 2; i++) {
            const int c = tid + i * 256;
            const int row = c >> 2, col = (c & 3) * 16;
            cp_async16(&smA[row * LDSS + col], A + (size_t)(bm + row) * K + k0 + col);
        }
        {
            const int row = tid >> 2, col = (tid & 3) * 16;
            cp_async16(&smB[row * LDSS + col], B + (size_t)(bn + row) * K + k0 + col);
        }
        cp_async_commit();
    };

    int32_t acc[2][4][4];
    #pragma unroll
    for (int mt = 0; mt < 2; mt++)
        #pragma unroll
        for (int nt = 0; nt < 4; nt++)
            #pragma unroll
            for (int i = 0; i < 4; i++)
                acc[mt][nt][i] = 0;

    // Prologue: stages 0,1
    load_tile(0, 0);
    load_tile(1, 1);

    for (int kt = 0; kt < KT; kt++) {
        if (kt + 2 < KT) cp_async_wait<1>();
        else             cp_async_wait<0>();
        __syncthreads();
        if (kt + 2 < KT) load_tile((kt + 2) % STAGES, kt + 2);

        const int st = kt % STAGES;
        const int8_t* smA = smem + st * STAGE_BYTES;
        const int8_t* smB = smA + A_ST;

        #pragma unroll
        for (int ki = 0; ki < 2; ki++) {        // two k32 steps inside BK=64
            const int kc = ki * 32 + q * 4;

            uint32_t af[2][4];
            #pragma unroll
            for (int mt = 0; mt < 2; mt++) {
                const int row = warpM * 32 + mt * 16 + g;
                const int8_t* base = &smA[row * LDSS + kc];
                af[mt][0] = *(const uint32_t*)(base);
                af[mt][1] = *(const uint32_t*)(base + 8 * LDSS);
                af[mt][2] = *(const uint32_t*)(base + 16);
                af[mt][3] = *(const uint32_t*)(base + 8 * LDSS + 16);
            }
            uint32_t bf[4][2];
            #pragma unroll
            for (int nt = 0; nt < 4; nt++) {
                const int nrow = warpN * 32 + nt * 8 + g;
                const int8_t* base = &smB[nrow * LDSS + kc];
                bf[nt][0] = *(const uint32_t*)(base);
                bf[nt][1] = *(const uint32_t*)(base + 16);
            }
            #pragma unroll
            for (int mt = 0; mt < 2; mt++)
                #pragma unroll
                for (int nt = 0; nt < 4; nt++)
                    mma_s8(acc[mt][nt], af[mt], bf[nt]);
        }
    }

    // Epilogue: dequant -> RNE -> clamp -> streaming store as FLOAT.
    const float scale = scale_x[0] * w_scale[0] / o_scale[0];

    #pragma unroll
    for (int mt = 0; mt < 2; mt++) {
        #pragma unroll
        for (int nt = 0; nt < 4; nt++) {
            const int row0 = bm + warpM * 32 + mt * 16 + g;
            const int col  = bn + warpN * 32 + nt * 8 + q * 2;
            #pragma unroll
            for (int half = 0; half < 2; half++) {
                const int row = row0 + half * 8;
                int v0 = __float2int_rn((float)acc[mt][nt][half * 2 + 0] * scale);
                int v1 = __float2int_rn((float)acc[mt][nt][half * 2 + 1] * scale);
                v0 = min(127, max(-128, v0));
                v1 = min(127, max(-128, v1));
                float2 o;
                o.x = (float)v0;
                o.y = (float)v1;
                __stcs((float2*)(C + (size_t)row * N + col), o);
            }
        }
    }
}

extern "C" void kernel_launch(void* const* d_in, const int* in_sizes, int n_in,
                              void* d_out, int out_size)
{
    // Identify inputs by element count (robust to metadata ordering).
    const void* x_ptr = nullptr;
    const void* w_ptr = nullptr;
    const float* scalars[3] = {nullptr, nullptr, nullptr};
    int ns = 0;
    for (int i = 0; i < n_in; i++) {
        long long sz = in_sizes[i];
        if (sz == (long long)M * K)      x_ptr = d_in[i];
        else if (sz == (long long)N * K) w_ptr = d_in[i];
        else if (ns < 3)                 scalars[ns++] = (const float*)d_in[i];
    }
    const float* scale_x = scalars[0];   // order: scale_x, weight_scale, out_scale
    const float* w_scale = scalars[1];
    const float* o_scale = scalars[2];
    float* out = (float*)d_out;

    static bool attr_done = false;
    if (!attr_done) {
        cudaFuncSetAttribute(int8_gemm_kernel,
                             cudaFuncAttributeMaxDynamicSharedMemorySize, SMEM_DYN);
        attr_done = true;
    }

    // Launch 1: decode inputs to int8 scratch + write output tail.
    {
        const int body = M * N;
        int n16 = (M * K + N * K) / 16;
        quantize_all_kernel<<<(n16 + 255) / 256, 256>>>(
            (const uint4*)x_ptr, (const uint4*)w_ptr,
            out, o_scale, body, out_size);
    }

    // Launch 2: the GEMM.
    dim3 grid(N / BN, M / BM);   // (64, 64) = 4096 CTAs
    int8_gemm_kernel<<<grid, 256, SMEM_DYN>>>(scale_x, w_scale, o_scale, out);
}

// round 16
// speedup vs baseline: 1.0595x; 1.0017x over previous
#include <cuda_runtime.h>
#include <cstdint>

// Problem dims (fixed by the reference)
static constexpr int M = 8192;
static constexpr int N = 4096;
static constexpr int K = 4096;

// Tiling: 128x64 CTA tile, BK=128, 2-stage double buffer, 3 CTAs/SM
// (24 warps in three independent 8-warp barrier domains; half the barriers
// of the BK=64 variant).
static constexpr int BM = 128;
static constexpr int BN = 64;
static constexpr int BK = 128;           // k-chunk bytes
static constexpr int LDSS = 144;         // smem row stride (128 data + 16 pad)
static constexpr int KT = K / BK;        // 32 k-chunks
static constexpr int STAGES = 2;
static constexpr int A_ST = BM * LDSS;   // 18432 B
static constexpr int B_ST = BN * LDSS;   // 9216 B
static constexpr int STAGE_BYTES = A_ST + B_ST;         // 27648 B
static constexpr int SMEM_DYN = STAGES * STAGE_BYTES;   // 55296 B (x3 = 166 KB/SM)

// int8 scratch (pre-quantized inputs). __device__ globals = allowed scratch.
__device__ int8_t g_xq[(size_t)M * K];   // 32 MB
__device__ int8_t g_wq[(size_t)N * K];   // 16 MB

__device__ __forceinline__ void cp_async16(void* smem_dst, const void* gmem_src) {
    uint32_t s = (uint32_t)__cvta_generic_to_shared(smem_dst);
    asm volatile("cp.async.cg.shared.global [%0], [%1], 16;\n" :: "r"(s), "l"(gmem_src));
}
__device__ __forceinline__ void cp_async_commit() {
    asm volatile("cp.async.commit_group;\n");
}
template <int NN>
__device__ __forceinline__ void cp_async_wait() {
    asm volatile("cp.async.wait_group %0;\n" :: "n"(NN));
}

__device__ __forceinline__ void mma_s8(int32_t* c, const uint32_t* a, const uint32_t* b) {
    asm volatile(
        "mma.sync.aligned.m16n8k32.row.col.s32.s8.s8.s32 "
        "{%0,%1,%2,%3}, {%4,%5,%6,%7}, {%8,%9}, {%0,%1,%2,%3};\n"
        : "+r"(c[0]), "+r"(c[1]), "+r"(c[2]), "+r"(c[3])
        : "r"(a[0]), "r"(a[1]), "r"(a[2]), "r"(a[3]),
          "r"(b[0]), "r"(b[1]));
}

// ---------------------------------------------------------------------------
// Pre-pass: dtype-agnostic word decode -> packed int8 (proven math).
// 16 elements per thread; streaming loads. At its HBM floor (~40 us).
// ---------------------------------------------------------------------------
__device__ __forceinline__ int8_t decode_q(uint32_t bits) {
    int iv = (int)bits;
    if ((unsigned)(iv + 128) <= 255u) return (int8_t)iv;
    float f = __int_as_float((int)bits);
    int v = __float2int_rn(f);
    v = min(127, max(-128, v));
    return (int8_t)v;
}

__device__ __forceinline__ uint32_t decode4(uint4 v) {
    uint32_t b0 = (uint8_t)decode_q(v.x);
    uint32_t b1 = (uint8_t)decode_q(v.y);
    uint32_t b2 = (uint8_t)decode_q(v.z);
    uint32_t b3 = (uint8_t)decode_q(v.w);
    return b0 | (b1 << 8) | (b2 << 16) | (b3 << 24);
}

__global__ void quantize_all_kernel(const uint4* __restrict__ x_in,
                                    const uint4* __restrict__ w_in,
                                    float* __restrict__ out,
                                    const float* __restrict__ o_scale,
                                    int body, int out_total)
{
    const int n16x = (M * K) / 16;
    const int n16w = (N * K) / 16;
    int i = blockIdx.x * blockDim.x + threadIdx.x;
    if (i < n16x) {
        uint4 o;
        o.x = decode4(__ldcs(&x_in[i * 4 + 0]));
        o.y = decode4(__ldcs(&x_in[i * 4 + 1]));
        o.z = decode4(__ldcs(&x_in[i * 4 + 2]));
        o.w = decode4(__ldcs(&x_in[i * 4 + 3]));
        ((uint4*)g_xq)[i] = o;
    } else if (i < n16x + n16w) {
        int j = i - n16x;
        uint4 o;
        o.x = decode4(__ldcs(&w_in[j * 4 + 0]));
        o.y = decode4(__ldcs(&w_in[j * 4 + 1]));
        o.z = decode4(__ldcs(&w_in[j * 4 + 2]));
        o.w = decode4(__ldcs(&w_in[j * 4 + 3]));
        ((uint4*)g_wq)[j] = o;
    }
    if (blockIdx.x == 0) {
        for (int idx = body + threadIdx.x; idx < out_total; idx += blockDim.x)
            out[idx] = o_scale[0];
    }
}

// ---------------------------------------------------------------------------
// int8 GEMM: C[m,n] = sum_k A[m,k]*B[n,k]. 128x64 CTA tile, BK=128,
// 2-stage double buffer, one __syncthreads per k-tile (32 total),
// loads issued AFTER the barrier (stage (kt+1)%2 free past compute(kt-1)).
// 8 warps: 4 M-slabs x 2 N-slabs of 32x32 each. acc = 32 regs/thread.
// ---------------------------------------------------------------------------
__global__ __launch_bounds__(256, 3)
void int8_gemm_kernel(const float* __restrict__ scale_x,
                      const float* __restrict__ w_scale,
                      const float* __restrict__ o_scale,
                      float* __restrict__ C)             // [M, N] f32 output
{
    extern __shared__ int8_t smem[];
    const int8_t* __restrict__ A = g_xq;
    const int8_t* __restrict__ B = g_wq;

    const int tid  = threadIdx.x;
    const int warp = tid >> 5;
    const int lane = tid & 31;
    const int warpM = warp >> 1;      // 0..3 -> 32-row slab
    const int warpN = warp & 1;       // 0..1 -> 32-col slab
    const int g = lane >> 2;          // group id 0..7
    const int q = lane & 3;           // thread-in-group 0..3

    const int bm = blockIdx.y * BM;
    const int bn = blockIdx.x * BN;

    // cp.async mapping: A = 128x128B = 1024 x16B chunks (4/thread);
    //                   B =  64x128B =  512 x16B chunks (2/thread).
    auto load_tile = [&](int stage, int kt) {
        int8_t* smA = smem + stage * STAGE_BYTES;
        int8_t* smB = smA + A_ST;
        const int k0 = kt * BK;
        #pragma unroll
        for (int i = 0; i < 4; i++) {
            const int c = tid + i * 256;
            const int row = c >> 3, col = (c & 7) * 16;
            cp_async16(&smA[row * LDSS + col], A + (size_t)(bm + row) * K + k0 + col);
        }
        #pragma unroll
        for (int i = 0; i < 2; i++) {
            const int c = tid + i * 256;
            const int row = c >> 3, col = (c & 7) * 16;
            cp_async16(&smB[row * LDSS + col], B + (size_t)(bn + row) * K + k0 + col);
        }
        cp_async_commit();
    };

    int32_t acc[2][4][4];
    #pragma unroll
    for (int mt = 0; mt < 2; mt++)
        #pragma unroll
        for (int nt = 0; nt < 4; nt++)
            #pragma unroll
            for (int i = 0; i < 4; i++)
                acc[mt][nt][i] = 0;

    // Prologue: stage 0
    load_tile(0, 0);

    for (int kt = 0; kt < KT; kt++) {
        cp_async_wait<0>();          // drain load(kt)
        __syncthreads();             // publish; all threads past compute(kt-1)
        if (kt + 1 < KT) load_tile((kt + 1) & 1, kt + 1);   // overlaps compute(kt)

        const int st = kt & 1;
        const int8_t* smA = smem + st * STAGE_BYTES;
        const int8_t* smB = smA + A_ST;

        #pragma unroll
        for (int ki = 0; ki < 4; ki++) {        // four k32 steps inside BK=128
            const int kc = ki * 32 + q * 4;

            uint32_t af[2][4];
            #pragma unroll
            for (int mt = 0; mt < 2; mt++) {
                const int row = warpM * 32 + mt * 16 + g;
                const int8_t* base = &smA[row * LDSS + kc];
                af[mt][0] = *(const uint32_t*)(base);
                af[mt][1] = *(const uint32_t*)(base + 8 * LDSS);
                af[mt][2] = *(const uint32_t*)(base + 16);
                af[mt][3] = *(const uint32_t*)(base + 8 * LDSS + 16);
            }
            uint32_t bf[4][2];
            #pragma unroll
            for (int nt = 0; nt < 4; nt++) {
                const int nrow = warpN * 32 + nt * 8 + g;
                const int8_t* base = &smB[nrow * LDSS + kc];
                bf[nt][0] = *(const uint32_t*)(base);
                bf[nt][1] = *(const uint32_t*)(base + 16);
            }
            #pragma unroll
            for (int mt = 0; mt < 2; mt++)
                #pragma unroll
                for (int nt = 0; nt < 4; nt++)
                    mma_s8(acc[mt][nt], af[mt], bf[nt]);
        }
    }

    // Epilogue: dequant -> RNE -> clamp -> streaming store as FLOAT.
    const float scale = scale_x[0] * w_scale[0] / o_scale[0];

    #pragma unroll
    for (int mt = 0; mt < 2; mt++) {
        #pragma unroll
        for (int nt = 0; nt < 4; nt++) {
            const int row0 = bm + warpM * 32 + mt * 16 + g;
            const int col  = bn + warpN * 32 + nt * 8 + q * 2;
            #pragma unroll
            for (int half = 0; half < 2; half++) {
                const int row = row0 + half * 8;
                int v0 = __float2int_rn((float)acc[mt][nt][half * 2 + 0] * scale);
                int v1 = __float2int_rn((float)acc[mt][nt][half * 2 + 1] * scale);
                v0 = min(127, max(-128, v0));
                v1 = min(127, max(-128, v1));
                float2 o;
                o.x = (float)v0;
                o.y = (float)v1;
                __stcs((float2*)(C + (size_t)row * N + col), o);
            }
        }
    }
}

extern "C" void kernel_launch(void* const* d_in, const int* in_sizes, int n_in,
                              void* d_out, int out_size)
{
    // Identify inputs by element count (robust to metadata ordering).
    const void* x_ptr = nullptr;
    const void* w_ptr = nullptr;
    const float* scalars[3] = {nullptr, nullptr, nullptr};
    int ns = 0;
    for (int i = 0; i < n_in; i++) {
        long long sz = in_sizes[i];
        if (sz == (long long)M * K)      x_ptr = d_in[i];
        else if (sz == (long long)N * K) w_ptr = d_in[i];
        else if (ns < 3)                 scalars[ns++] = (const float*)d_in[i];
    }
    const float* scale_x = scalars[0];   // order: scale_x, weight_scale, out_scale
    const float* w_scale = scalars[1];
    const float* o_scale = scalars[2];
    float* out = (float*)d_out;

    static bool attr_done = false;
    if (!attr_done) {
        cudaFuncSetAttribute(int8_gemm_kernel,
                             cudaFuncAttributeMaxDynamicSharedMemorySize, SMEM_DYN);
        attr_done = true;
    }

    // Launch 1: decode inputs to int8 scratch + write output tail.
    {
        const int body = M * N;
        int n16 = (M * K + N * K) / 16;
        quantize_all_kernel<<<(n16 + 255) / 256, 256>>>(
            (const uint4*)x_ptr, (const uint4*)w_ptr,
            out, o_scale, body, out_size);
    }

    // Launch 2: the GEMM.
    dim3 grid(N / BN, M / BM);   // (64, 64) = 4096 CTAs
    int8_gemm_kernel<<<grid, 256, SMEM_DYN>>>(scale_x, w_scale, o_scale, out);
}